// round 16
// baseline (speedup 1.0000x reference)
#include <cuda_runtime.h>
#include <cuda_bf16.h>
#include <mma.h>
#include <cstdint>
#include <math.h>

using namespace nvcuda;

#define HN   12
#define TT   1024
#define DD   64
#define DINE 768
#define NBB  4
#define NTR  (NBB*TT)   // 4096
#define NBH  (NBB*HN)   // 48

// Scratch (static device globals — allocation-free)
__device__ __nv_bfloat16 g_x_hi[NTR*DINE];
__device__ __nv_bfloat16 g_x_lo[NTR*DINE];
__device__ __nv_bfloat16 g_w_hi[36*DINE*DD];   // [mh][k][n]
__device__ __nv_bfloat16 g_w_lo[36*DINE*DD];
__device__ __nv_bfloat16 g_wo_h[DINE*DD], g_wo_l[DINE*DD];
__device__ __nv_bfloat16 g_qh[NBH*TT*DD], g_ql[NBH*TT*DD];
__device__ __nv_bfloat16 g_kh[NBH*TT*DD], g_kl[NBH*TT*DD];
__device__ __nv_bfloat16 g_vh[NBH*TT*DD], g_vl[NBH*TT*DD];
__device__ __nv_bfloat16 g_oh[NTR*DINE], g_ol[NTR*DINE];

// Side stream + events for fork/join overlap (created once, pre-main; no
// device memory allocation involved). Fallback to single-stream if creation
// fails.
static cudaStream_t g_s1 = nullptr;
static cudaEvent_t  g_evCvt = nullptr, g_evV = nullptr;
static struct StreamInit {
    StreamInit() {
        if (cudaStreamCreateWithFlags(&g_s1, cudaStreamNonBlocking) != cudaSuccess)
            g_s1 = nullptr;
        if (g_s1) {
            if (cudaEventCreateWithFlags(&g_evCvt, cudaEventDisableTiming) != cudaSuccess ||
                cudaEventCreateWithFlags(&g_evV,  cudaEventDisableTiming) != cudaSuccess)
                g_s1 = nullptr;
        }
    }
} g_stream_init;

// Fast exp on the FMA pipe. x <= 0 expected (handles -inf via clamp).
__device__ __forceinline__ float fexp(float x) {
    x = fmaxf(x, -87.0f);
    float y = x * 1.44269504088896f;
    int   n = __float2int_rn(y);
    float f = y - (float)n;
    float p = 1.53989348e-4f;
    p = fmaf(p, f, 1.33336246e-3f);
    p = fmaf(p, f, 9.61812910e-3f);
    p = fmaf(p, f, 5.55041087e-2f);
    p = fmaf(p, f, 2.40226507e-1f);
    p = fmaf(p, f, 6.93147181e-1f);
    p = fmaf(p, f, 1.0f);
    return p * __int_as_float((n + 127) << 23);
}

__device__ __forceinline__ void split4(float4 v, __nv_bfloat162* hh, __nv_bfloat162* ll) {
    hh[0] = __floats2bfloat162_rn(v.x, v.y);
    hh[1] = __floats2bfloat162_rn(v.z, v.w);
    float2 f0 = __bfloat1622float2(hh[0]);
    float2 f1 = __bfloat1622float2(hh[1]);
    ll[0] = __floats2bfloat162_rn(v.x - f0.x, v.y - f0.y);
    ll[1] = __floats2bfloat162_rn(v.z - f1.x, v.w - f1.y);
}

// ---------------------------------------------------------------------------
// Converters
// ---------------------------------------------------------------------------
__global__ __launch_bounds__(256) void cvt_x_kernel(const float* __restrict__ x)
{
    int i = blockIdx.x * 256 + threadIdx.x;
    float4 v = ((const float4*)x)[i];
    __nv_bfloat162 hh[2], ll[2];
    split4(v, hh, ll);
    ((__nv_bfloat162*)g_x_hi)[2*i]   = hh[0];
    ((__nv_bfloat162*)g_x_hi)[2*i+1] = hh[1];
    ((__nv_bfloat162*)g_x_lo)[2*i]   = ll[0];
    ((__nv_bfloat162*)g_x_lo)[2*i+1] = ll[1];
}

__global__ __launch_bounds__(256) void cvt_w_kernel(
    const float* __restrict__ Wq, const float* __restrict__ Wk,
    const float* __restrict__ Wv)
{
    int mat = blockIdx.y;
    const float* Wm = (mat == 0 ? Wq : mat == 1 ? Wk : Wv);
    size_t base = (size_t)mat * HN * DINE * DD;
    int i = blockIdx.x * 256 + threadIdx.x;
    float4 v = ((const float4*)Wm)[i];
    __nv_bfloat162 hh[2], ll[2];
    split4(v, hh, ll);
    ((__nv_bfloat162*)(g_w_hi + base))[2*i]   = hh[0];
    ((__nv_bfloat162*)(g_w_hi + base))[2*i+1] = hh[1];
    ((__nv_bfloat162*)(g_w_lo + base))[2*i]   = ll[0];
    ((__nv_bfloat162*)(g_w_lo + base))[2*i+1] = ll[1];
}

__global__ __launch_bounds__(256) void cvt_wo_kernel(const float* __restrict__ Wo)
{
    int i = blockIdx.x * 256 + threadIdx.x;   // 12288 float4
    float4 v = ((const float4*)Wo)[i];
    __nv_bfloat162 hh[2], ll[2];
    split4(v, hh, ll);
    ((__nv_bfloat162*)g_wo_h)[2*i]   = hh[0];
    ((__nv_bfloat162*)g_wo_h)[2*i+1] = hh[1];
    ((__nv_bfloat162*)g_wo_l)[2*i]   = ll[0];
    ((__nv_bfloat162*)g_wo_l)[2*i+1] = ll[1];
}

// ---------------------------------------------------------------------------
// QKV via WMMA bf16 split: 2 heads per CTA (R11 body). cbk0 = column-block
// offset so QK (cbk 0..11) and V (cbk 12..17) can launch separately.
// ---------------------------------------------------------------------------
#define ASTR 72
#define BSTR2 136
#define QKV_SMEM 71680   // A 2*128*72*2 + B 2*64*136*2; epi fp32 128*132*4 fits

__global__ __launch_bounds__(256) void qkv_tc_kernel(int cbk0)
{
    extern __shared__ __align__(16) char dyn[];
    __nv_bfloat16* sAh = (__nv_bfloat16*)dyn;              // 128*ASTR
    __nv_bfloat16* sAl = sAh + 128*ASTR;
    __nv_bfloat16* sBh = sAl + 128*ASTR;                   // 64*BSTR2
    __nv_bfloat16* sBl = sBh + 64*BSTR2;
    float* sC = (float*)dyn;                               // epi: 128 x 132

    int rt = blockIdx.x;
    int cbk = blockIdx.y + cbk0;
    int mat = cbk / 6, hp = cbk % 6, h0 = 2 * hp;
    int row0 = rt * 128;
    int tid = threadIdx.x, warp = tid >> 5;
    int wm = warp & 3, wn = warp >> 2;

    wmma::fragment<wmma::accumulator, 16, 16, 16, float> c[2][4];
#pragma unroll
    for (int mi = 0; mi < 2; mi++)
#pragma unroll
        for (int ni = 0; ni < 4; ni++) wmma::fill_fragment(c[mi][ni], 0.0f);

    for (int k0 = 0; k0 < DINE; k0 += 64) {
#pragma unroll
        for (int it = 0; it < 4; it++) {
            int idx = tid + 256 * it;
            int r = idx >> 3, cc = (idx & 7) * 8;
            size_t src = (size_t)(row0 + r) * DINE + k0 + cc;
            *(uint4*)&sAh[r*ASTR + cc] = *(const uint4*)&g_x_hi[src];
            *(uint4*)&sAl[r*ASTR + cc] = *(const uint4*)&g_x_lo[src];
        }
#pragma unroll
        for (int it = 0; it < 4; it++) {
            int idx = tid + 256 * it;
            int r = idx >> 4, c8 = (idx & 15) * 8;
            int mh = mat * HN + h0 + (c8 >> 6);
            int d0 = c8 & 63;
            size_t src = ((size_t)mh * DINE + (k0 + r)) * DD + d0;
            *(uint4*)&sBh[r*BSTR2 + c8] = *(const uint4*)&g_w_hi[src];
            *(uint4*)&sBl[r*BSTR2 + c8] = *(const uint4*)&g_w_lo[src];
        }
        __syncthreads();

#pragma unroll
        for (int ks = 0; ks < 64; ks += 16) {
            wmma::fragment<wmma::matrix_a, 16, 16, 16, __nv_bfloat16, wmma::row_major> ah[2], al[2];
#pragma unroll
            for (int mi = 0; mi < 2; mi++) {
                wmma::load_matrix_sync(ah[mi], &sAh[(wm*32 + mi*16)*ASTR + ks], ASTR);
                wmma::load_matrix_sync(al[mi], &sAl[(wm*32 + mi*16)*ASTR + ks], ASTR);
            }
#pragma unroll
            for (int ni = 0; ni < 4; ni++) {
                wmma::fragment<wmma::matrix_b, 16, 16, 16, __nv_bfloat16, wmma::row_major> bh, bl;
                wmma::load_matrix_sync(bh, &sBh[ks*BSTR2 + wn*64 + ni*16], BSTR2);
                wmma::load_matrix_sync(bl, &sBl[ks*BSTR2 + wn*64 + ni*16], BSTR2);
#pragma unroll
                for (int mi = 0; mi < 2; mi++) {
                    wmma::mma_sync(c[mi][ni], ah[mi], bh, c[mi][ni]);
                    wmma::mma_sync(c[mi][ni], ah[mi], bl, c[mi][ni]);
                    wmma::mma_sync(c[mi][ni], al[mi], bh, c[mi][ni]);
                }
            }
        }
        __syncthreads();
    }

#pragma unroll
    for (int mi = 0; mi < 2; mi++)
#pragma unroll
        for (int ni = 0; ni < 4; ni++)
            wmma::store_matrix_sync(&sC[(wm*32 + mi*16)*132 + wn*64 + ni*16],
                                    c[mi][ni], 132, wmma::mem_row_major);
    __syncthreads();

    __nv_bfloat16* dh = (mat == 0 ? g_qh : mat == 1 ? g_kh : g_vh);
    __nv_bfloat16* dl = (mat == 0 ? g_ql : mat == 1 ? g_kl : g_vl);
    int n = row0 >> 10, t0 = row0 & (TT - 1);
#pragma unroll
    for (int it = 0; it < 8; it++) {
        int idx = tid + 256 * it;
        int r = idx >> 4, c8 = (idx & 15) * 8;
        int h = h0 + (c8 >> 6), d0 = c8 & 63;
        size_t base = ((size_t)(n*HN + h)*TT + t0 + r) * DD + d0;
        const float* src = &sC[r*132 + c8];
        __nv_bfloat162 hh[4], ll[4];
#pragma unroll
        for (int q = 0; q < 2; q++) {
            float4 v = *(const float4*)&src[4*q];
            split4(v, &hh[2*q], &ll[2*q]);
        }
        *(uint4*)&dh[base] = *(uint4*)hh;
        *(uint4*)&dl[base] = *(uint4*)ll;
    }
}

// ---------------------------------------------------------------------------
// S = Q @ K^T via WMMA bf16 split, per (bh, lower-tri 128x128 block).
// ---------------------------------------------------------------------------
#define QS 72
__global__ __launch_bounds__(256, 2) void sgemm_tc_kernel(float* __restrict__ attn)
{
    extern __shared__ __nv_bfloat16 smb[];
    __nv_bfloat16* sQh = smb;
    __nv_bfloat16* sQl = smb + 128*QS;
    __nv_bfloat16* sKh = smb + 2*128*QS;
    __nv_bfloat16* sKl = smb + 3*128*QS;

    int idx = blockIdx.x, rb = 0;
    while (idx > rb) { idx -= rb + 1; rb++; }
    int cb = idx;
    int bh = blockIdx.y;

    const __nv_bfloat16* qh = g_qh + ((size_t)bh * TT + rb*128) * DD;
    const __nv_bfloat16* ql = g_ql + ((size_t)bh * TT + rb*128) * DD;
    const __nv_bfloat16* kh = g_kh + ((size_t)bh * TT + cb*128) * DD;
    const __nv_bfloat16* kl = g_kl + ((size_t)bh * TT + cb*128) * DD;

    int tid = threadIdx.x, warp = tid >> 5;
    int wm = warp & 3, wn = warp >> 2;

#pragma unroll
    for (int it = 0; it < 4; it++) {
        int v = tid + 256 * it;
        int r = v >> 3, cc = (v & 7) * 8;
        *(uint4*)&sQh[r*QS + cc] = *(const uint4*)&qh[(size_t)r*DD + cc];
        *(uint4*)&sQl[r*QS + cc] = *(const uint4*)&ql[(size_t)r*DD + cc];
        *(uint4*)&sKh[r*QS + cc] = *(const uint4*)&kh[(size_t)r*DD + cc];
        *(uint4*)&sKl[r*QS + cc] = *(const uint4*)&kl[(size_t)r*DD + cc];
    }
    __syncthreads();

    wmma::fragment<wmma::accumulator, 16, 16, 16, float> c[2][4];
#pragma unroll
    for (int mi = 0; mi < 2; mi++)
#pragma unroll
        for (int ni = 0; ni < 4; ni++) wmma::fill_fragment(c[mi][ni], 0.0f);

#pragma unroll
    for (int k0 = 0; k0 < 64; k0 += 16) {
        wmma::fragment<wmma::matrix_a, 16, 16, 16, __nv_bfloat16, wmma::row_major> ah[2], al[2];
#pragma unroll
        for (int mi = 0; mi < 2; mi++) {
            wmma::load_matrix_sync(ah[mi], &sQh[(wm*32 + mi*16)*QS + k0], QS);
            wmma::load_matrix_sync(al[mi], &sQl[(wm*32 + mi*16)*QS + k0], QS);
        }
#pragma unroll
        for (int ni = 0; ni < 4; ni++) {
            wmma::fragment<wmma::matrix_b, 16, 16, 16, __nv_bfloat16, wmma::col_major> bh, bl;
            wmma::load_matrix_sync(bh, &sKh[(wn*64 + ni*16)*QS + k0], QS);
            wmma::load_matrix_sync(bl, &sKl[(wn*64 + ni*16)*QS + k0], QS);
#pragma unroll
            for (int mi = 0; mi < 2; mi++) {
                wmma::mma_sync(c[mi][ni], ah[mi], bh, c[mi][ni]);
                wmma::mma_sync(c[mi][ni], ah[mi], bl, c[mi][ni]);
                wmma::mma_sync(c[mi][ni], al[mi], bh, c[mi][ni]);
            }
        }
    }

#pragma unroll
    for (int mi = 0; mi < 2; mi++)
#pragma unroll
        for (int ni = 0; ni < 4; ni++) {
            int row = rb*128 + wm*32 + mi*16;
            int col = cb*128 + wn*64 + ni*16;
            wmma::store_matrix_sync(&attn[((size_t)bh*TT + row)*TT + col],
                                    c[mi][ni], TT, wmma::mem_row_major);
        }
}

// ---------------------------------------------------------------------------
// Softmax (causal + "==0 -> -inf"), one warp/row, float4, dead-block skip.
// ---------------------------------------------------------------------------
__global__ __launch_bounds__(256) void softmax_kernel(float* __restrict__ attn)
{
    int tid = threadIdx.x, lane = tid & 31, warp = tid >> 5;
    int tq = blockIdx.x * 8 + warp;
    int bh = blockIdx.y;
    float* row = attn + ((size_t)bh * TT + tq) * TT;
    int len = tq + 1;
    int jlim = (len + 127) >> 7;

    float4 pv4[8];
    float mx = -INFINITY;
#pragma unroll
    for (int j = 0; j < 8; j++) {
        if (j < jlim) {
            int base = j*128 + lane*4;
            float4 v = *(const float4*)&row[base];
            float* e = &v.x;
#pragma unroll
            for (int cq = 0; cq < 4; cq++) {
                float val = (base + cq < len) ? (e[cq] == 0.0f ? -INFINITY : e[cq])
                                              : -INFINITY;
                e[cq] = val;
                mx = fmaxf(mx, val);
            }
            pv4[j] = v;
        } else {
            pv4[j] = make_float4(0.f, 0.f, 0.f, 0.f);
        }
    }
#pragma unroll
    for (int o = 16; o > 0; o >>= 1) mx = fmaxf(mx, __shfl_xor_sync(0xffffffffu, mx, o));

    float sum = 0.f;
#pragma unroll
    for (int j = 0; j < 8; j++) {
        if (j < jlim) {
            int base = j*128 + lane*4;
            float* e = &pv4[j].x;
#pragma unroll
            for (int cq = 0; cq < 4; cq++) {
                float p = (base + cq < len) ? fexp(e[cq] - mx) : 0.0f;
                e[cq] = p;
                sum += p;
            }
        }
    }
#pragma unroll
    for (int o = 16; o > 0; o >>= 1) sum += __shfl_xor_sync(0xffffffffu, sum, o);
    float inv = 1.f / sum;

#pragma unroll
    for (int j = 0; j < 8; j++) {
        float4 v = pv4[j];
        v.x *= inv; v.y *= inv; v.z *= inv; v.w *= inv;
        *(float4*)&row[j*128 + lane*4] = v;
    }
}

// ---------------------------------------------------------------------------
// O = P @ V via WMMA, key-chunk 64. Epilogue writes bf16 hi/lo O.
// ---------------------------------------------------------------------------
#define PVS 72
#define PV_SMEM 55296   // P 2*128*72*2 + V 2*64*72*2; epi 128*68*4=34816 fits

__global__ __launch_bounds__(256) void pv_tc_kernel(const float* __restrict__ attn)
{
    extern __shared__ __align__(16) char dynp[];
    __nv_bfloat16* sPh = (__nv_bfloat16*)dynp;           // 128*PVS
    __nv_bfloat16* sPl = sPh + 128*PVS;
    __nv_bfloat16* sVh = sPl + 128*PVS;                  // 64*PVS
    __nv_bfloat16* sVl = sVh + 64*PVS;
    float* sC = (float*)dynp;                            // epi: 128 x 68

    int rb = 7 - blockIdx.x;
    int bh = blockIdx.y;
    int row0 = rb * 128;
    int kmax = (rb + 1) * 128;
    const float* pp = attn + ((size_t)bh * TT + row0) * TT;
    const __nv_bfloat16* vh = g_vh + (size_t)bh * TT * DD;
    const __nv_bfloat16* vl = g_vl + (size_t)bh * TT * DD;

    int tid = threadIdx.x, warp = tid >> 5;
    int wm = warp & 3, wn = warp >> 2;

    wmma::fragment<wmma::accumulator, 16, 16, 16, float> c[2][2];
#pragma unroll
    for (int mi = 0; mi < 2; mi++)
#pragma unroll
        for (int ni = 0; ni < 2; ni++) wmma::fill_fragment(c[mi][ni], 0.0f);

    for (int sb = 0; sb < kmax; sb += 64) {
#pragma unroll
        for (int it = 0; it < 8; it++) {
            int v = tid + 256 * it;
            int r = v >> 4, c4 = (v & 15) * 4;
            float4 p = *(const float4*)&pp[(size_t)r * TT + sb + c4];
            __nv_bfloat162 hh[2], ll[2];
            split4(p, hh, ll);
            *(__nv_bfloat162*)&sPh[r*PVS + c4]     = hh[0];
            *(__nv_bfloat162*)&sPh[r*PVS + c4 + 2] = hh[1];
            *(__nv_bfloat162*)&sPl[r*PVS + c4]     = ll[0];
            *(__nv_bfloat162*)&sPl[r*PVS + c4 + 2] = ll[1];
        }
#pragma unroll
        for (int it = 0; it < 2; it++) {
            int v = tid + 256 * it;
            int r = v >> 3, cc = (v & 7) * 8;
            *(uint4*)&sVh[r*PVS + cc] = *(const uint4*)&vh[(size_t)(sb + r)*DD + cc];
            *(uint4*)&sVl[r*PVS + cc] = *(const uint4*)&vl[(size_t)(sb + r)*DD + cc];
        }
        __syncthreads();

#pragma unroll
        for (int k0 = 0; k0 < 64; k0 += 16) {
            wmma::fragment<wmma::matrix_a, 16, 16, 16, __nv_bfloat16, wmma::row_major> ah[2], al[2];
#pragma unroll
            for (int mi = 0; mi < 2; mi++) {
                wmma::load_matrix_sync(ah[mi], &sPh[(wm*32 + mi*16)*PVS + k0], PVS);
                wmma::load_matrix_sync(al[mi], &sPl[(wm*32 + mi*16)*PVS + k0], PVS);
            }
#pragma unroll
            for (int ni = 0; ni < 2; ni++) {
                wmma::fragment<wmma::matrix_b, 16, 16, 16, __nv_bfloat16, wmma::row_major> bh, bl;
                wmma::load_matrix_sync(bh, &sVh[k0*PVS + wn*32 + ni*16], PVS);
                wmma::load_matrix_sync(bl, &sVl[k0*PVS + wn*32 + ni*16], PVS);
#pragma unroll
                for (int mi = 0; mi < 2; mi++) {
                    wmma::mma_sync(c[mi][ni], ah[mi], bh, c[mi][ni]);
                    wmma::mma_sync(c[mi][ni], ah[mi], bl, c[mi][ni]);
                    wmma::mma_sync(c[mi][ni], al[mi], bh, c[mi][ni]);
                }
            }
        }
        __syncthreads();
    }

    // Epilogue: frags -> smem fp32 -> bf16 hi/lo O
#pragma unroll
    for (int mi = 0; mi < 2; mi++)
#pragma unroll
        for (int ni = 0; ni < 2; ni++)
            wmma::store_matrix_sync(&sC[(wm*32 + mi*16)*68 + wn*32 + ni*16],
                                    c[mi][ni], 68, wmma::mem_row_major);
    __syncthreads();

    int n = bh / HN, h = bh % HN;
#pragma unroll
    for (int it = 0; it < 4; it++) {
        int idx = tid + 256 * it;
        int r = idx >> 3, d0 = (idx & 7) * 8;
        size_t base = ((size_t)(n*TT + row0 + r))*DINE + h*DD + d0;
        const float* src = &sC[r*68 + d0];
        __nv_bfloat162 hh[4], ll[4];
#pragma unroll
        for (int q = 0; q < 2; q++) {
            float4 v = *(const float4*)&src[4*q];
            split4(v, &hh[2*q], &ll[2*q]);
        }
        *(uint4*)&g_oh[base] = *(uint4*)hh;
        *(uint4*)&g_ol[base] = *(uint4*)ll;
    }
}

// ---------------------------------------------------------------------------
// Output projection via WMMA: out = O @ Wo + bo. grid 128 x 32 rows.
// ---------------------------------------------------------------------------
#define OP_SMEM 27648

__global__ __launch_bounds__(256) void oproj_tc_kernel(
    const float* __restrict__ bo, float* __restrict__ out)
{
    extern __shared__ __align__(16) char dyno[];
    __nv_bfloat16* sAh = (__nv_bfloat16*)dyno;           // 32*PVS
    __nv_bfloat16* sAl = sAh + 32*PVS;
    __nv_bfloat16* sBh = sAl + 32*PVS;                   // 64*PVS
    __nv_bfloat16* sBl = sBh + 64*PVS;
    float* sC = (float*)dyno;                            // epi: 32 x 68

    int row0 = blockIdx.x * 32;
    int tid = threadIdx.x, warp = tid >> 5;
    int wm = warp & 1, wn = warp >> 1;   // warp tile 16x16

    wmma::fragment<wmma::accumulator, 16, 16, 16, float> c;
    wmma::fill_fragment(c, 0.0f);

    for (int k0 = 0; k0 < DINE; k0 += 64) {
        {
            int r = tid >> 3, cc = (tid & 7) * 8;
            size_t src = (size_t)(row0 + r) * DINE + k0 + cc;
            *(uint4*)&sAh[r*PVS + cc] = *(const uint4*)&g_oh[src];
            *(uint4*)&sAl[r*PVS + cc] = *(const uint4*)&g_ol[src];
        }
#pragma unroll
        for (int it = 0; it < 2; it++) {
            int idx = tid + 256 * it;
            int r = idx >> 3, cc = (idx & 7) * 8;
            size_t src = (size_t)(k0 + r) * DD + cc;
            *(uint4*)&sBh[r*PVS + cc] = *(const uint4*)&g_wo_h[src];
            *(uint4*)&sBl[r*PVS + cc] = *(const uint4*)&g_wo_l[src];
        }
        __syncthreads();

#pragma unroll
        for (int ks = 0; ks < 64; ks += 16) {
            wmma::fragment<wmma::matrix_a, 16, 16, 16, __nv_bfloat16, wmma::row_major> ah, al;
            wmma::fragment<wmma::matrix_b, 16, 16, 16, __nv_bfloat16, wmma::row_major> bh, bl;
            wmma::load_matrix_sync(ah, &sAh[(wm*16)*PVS + ks], PVS);
            wmma::load_matrix_sync(al, &sAl[(wm*16)*PVS + ks], PVS);
            wmma::load_matrix_sync(bh, &sBh[ks*PVS + wn*16], PVS);
            wmma::load_matrix_sync(bl, &sBl[ks*PVS + wn*16], PVS);
            wmma::mma_sync(c, ah, bh, c);
            wmma::mma_sync(c, ah, bl, c);
            wmma::mma_sync(c, al, bh, c);
        }
        __syncthreads();
    }

    wmma::store_matrix_sync(&sC[(wm*16)*68 + wn*16], c, 68, wmma::mem_row_major);
    __syncthreads();

#pragma unroll
    for (int it = 0; it < 2; it++) {
        int idx = tid + 256 * it;
        int r = idx >> 4, c4 = (idx & 15) * 4;
        float4 b = *(const float4*)&bo[c4];
        const float* src = &sC[r*68 + c4];
        float4 v = make_float4(src[0]+b.x, src[1]+b.y, src[2]+b.z, src[3]+b.w);
        *(float4*)&out[(size_t)(row0 + r) * DD + c4] = v;
    }
}

// ---------------------------------------------------------------------------
extern "C" void kernel_launch(void* const* d_in, const int* in_sizes, int n_in,
                              void* d_out, int out_size)
{
    const float* x  = (const float*)d_in[0];
    const float* Wq = (const float*)d_in[1];
    const float* Wk = (const float*)d_in[2];
    const float* Wv = (const float*)d_in[3];
    const float* Wo = (const float*)d_in[4];
    const float* bo = (const float*)d_in[5];
    float* out = (float*)d_out;

    const long NTD = (long)NBB * TT * DD;
    float* attn = out + NTD;

    cudaFuncSetAttribute(qkv_tc_kernel, cudaFuncAttributeMaxDynamicSharedMemorySize, QKV_SMEM);
    int smem_s = 4 * 128 * QS * (int)sizeof(__nv_bfloat16);  // 73728
    cudaFuncSetAttribute(sgemm_tc_kernel, cudaFuncAttributeMaxDynamicSharedMemorySize, smem_s);
    cudaFuncSetAttribute(pv_tc_kernel, cudaFuncAttributeMaxDynamicSharedMemorySize, PV_SMEM);
    cudaFuncSetAttribute(oproj_tc_kernel, cudaFuncAttributeMaxDynamicSharedMemorySize, OP_SMEM);

    cvt_x_kernel<<<3072, 256>>>(x);
    cvt_w_kernel<<<dim3(576, 3), 256>>>(Wq, Wk, Wv);

    if (g_s1) {
        // Fork: V projection + Wo conversion on side stream, hidden under
        // QK projection + S-GEMM + softmax on the main stream.
        cudaEventRecord(g_evCvt, 0);
        cudaStreamWaitEvent(g_s1, g_evCvt, 0);
        qkv_tc_kernel<<<dim3(32, 6), 256, QKV_SMEM, g_s1>>>(12);   // V
        cvt_wo_kernel<<<48, 256, 0, g_s1>>>(Wo);
        cudaEventRecord(g_evV, g_s1);

        qkv_tc_kernel<<<dim3(32, 12), 256, QKV_SMEM>>>(0);          // Q,K
        sgemm_tc_kernel<<<dim3(36, NBH), 256, smem_s>>>(attn);
        softmax_kernel<<<dim3(128, NBH), 256>>>(attn);

        cudaStreamWaitEvent(0, g_evV, 0);                           // join
        pv_tc_kernel<<<dim3(8, NBH), 256, PV_SMEM>>>(attn);
        oproj_tc_kernel<<<128, 256, OP_SMEM>>>(bo, out);
    } else {
        // Fallback: single-stream sequential (identical work)
        cvt_wo_kernel<<<48, 256>>>(Wo);
        qkv_tc_kernel<<<dim3(32, 12), 256, QKV_SMEM>>>(0);
        qkv_tc_kernel<<<dim3(32, 6), 256, QKV_SMEM>>>(12);
        sgemm_tc_kernel<<<dim3(36, NBH), 256, smem_s>>>(attn);
        softmax_kernel<<<dim3(128, NBH), 256>>>(attn);
        pv_tc_kernel<<<dim3(8, NBH), 256, PV_SMEM>>>(attn);
        oproj_tc_kernel<<<128, 256, OP_SMEM>>>(bo, out);
    }
}

// round 17
// speedup vs baseline: 1.0720x; 1.0720x over previous
#include <cuda_runtime.h>
#include <cuda_bf16.h>
#include <mma.h>
#include <cstdint>
#include <math.h>

using namespace nvcuda;

#define HN   12
#define TT   1024
#define DD   64
#define DINE 768
#define NBB  4
#define NTR  (NBB*TT)   // 4096
#define NBH  (NBB*HN)   // 48

// Scratch (static device globals — allocation-free)
__device__ __nv_bfloat16 g_w_hi[36*DINE*DD];   // [mh][k][n]
__device__ __nv_bfloat16 g_w_lo[36*DINE*DD];
__device__ __nv_bfloat16 g_wo_h[DINE*DD], g_wo_l[DINE*DD];
__device__ __nv_bfloat16 g_qh[NBH*TT*DD], g_ql[NBH*TT*DD];
__device__ __nv_bfloat16 g_kh[NBH*TT*DD], g_kl[NBH*TT*DD];
__device__ __nv_bfloat16 g_vh[NBH*TT*DD], g_vl[NBH*TT*DD];
__device__ __nv_bfloat16 g_oh[NTR*DINE], g_ol[NTR*DINE];

// Fast exp on the FMA pipe. x <= 0 expected (handles -inf via clamp).
__device__ __forceinline__ float fexp(float x) {
    x = fmaxf(x, -87.0f);
    float y = x * 1.44269504088896f;
    int   n = __float2int_rn(y);
    float f = y - (float)n;
    float p = 1.53989348e-4f;
    p = fmaf(p, f, 1.33336246e-3f);
    p = fmaf(p, f, 9.61812910e-3f);
    p = fmaf(p, f, 5.55041087e-2f);
    p = fmaf(p, f, 2.40226507e-1f);
    p = fmaf(p, f, 6.93147181e-1f);
    p = fmaf(p, f, 1.0f);
    return p * __int_as_float((n + 127) << 23);
}

__device__ __forceinline__ void split4(float4 v, __nv_bfloat162* hh, __nv_bfloat162* ll) {
    hh[0] = __floats2bfloat162_rn(v.x, v.y);
    hh[1] = __floats2bfloat162_rn(v.z, v.w);
    float2 f0 = __bfloat1622float2(hh[0]);
    float2 f1 = __bfloat1622float2(hh[1]);
    ll[0] = __floats2bfloat162_rn(v.x - f0.x, v.y - f0.y);
    ll[1] = __floats2bfloat162_rn(v.z - f1.x, v.w - f1.y);
}

// ---------------------------------------------------------------------------
// Converters (W and Wo only; X is split in-register inside qkv)
// ---------------------------------------------------------------------------
__global__ __launch_bounds__(256) void cvt_w_kernel(
    const float* __restrict__ Wq, const float* __restrict__ Wk,
    const float* __restrict__ Wv)
{
    int mat = blockIdx.y;
    const float* Wm = (mat == 0 ? Wq : mat == 1 ? Wk : Wv);
    size_t base = (size_t)mat * HN * DINE * DD;
    int i = blockIdx.x * 256 + threadIdx.x;
    float4 v = ((const float4*)Wm)[i];
    __nv_bfloat162 hh[2], ll[2];
    split4(v, hh, ll);
    ((__nv_bfloat162*)(g_w_hi + base))[2*i]   = hh[0];
    ((__nv_bfloat162*)(g_w_hi + base))[2*i+1] = hh[1];
    ((__nv_bfloat162*)(g_w_lo + base))[2*i]   = ll[0];
    ((__nv_bfloat162*)(g_w_lo + base))[2*i+1] = ll[1];
}

__global__ __launch_bounds__(256) void cvt_wo_kernel(const float* __restrict__ Wo)
{
    int i = blockIdx.x * 256 + threadIdx.x;   // 12288 float4
    float4 v = ((const float4*)Wo)[i];
    __nv_bfloat162 hh[2], ll[2];
    split4(v, hh, ll);
    ((__nv_bfloat162*)g_wo_h)[2*i]   = hh[0];
    ((__nv_bfloat162*)g_wo_h)[2*i+1] = hh[1];
    ((__nv_bfloat162*)g_wo_l)[2*i]   = ll[0];
    ((__nv_bfloat162*)g_wo_l)[2*i+1] = ll[1];
}

// ---------------------------------------------------------------------------
// QKV via WMMA bf16 split: 2 heads per CTA. X read as fp32 and split
// in-register into smem hi/lo (cvt_x pass eliminated).
// ---------------------------------------------------------------------------
#define ASTR 72
#define BSTR2 136
#define QKV_SMEM 71680   // A 2*128*72*2 + B 2*64*136*2; epi fp32 128*132*4 fits

__global__ __launch_bounds__(256) void qkv_tc_kernel(const float* __restrict__ x)
{
    extern __shared__ __align__(16) char dyn[];
    __nv_bfloat16* sAh = (__nv_bfloat16*)dyn;              // 128*ASTR
    __nv_bfloat16* sAl = sAh + 128*ASTR;
    __nv_bfloat16* sBh = sAl + 128*ASTR;                   // 64*BSTR2
    __nv_bfloat16* sBl = sBh + 64*BSTR2;
    float* sC = (float*)dyn;                               // epi: 128 x 132

    int rt = blockIdx.x;
    int cbk = blockIdx.y;
    int mat = cbk / 6, hp = cbk % 6, h0 = 2 * hp;
    int row0 = rt * 128;
    int tid = threadIdx.x, warp = tid >> 5;
    int wm = warp & 3, wn = warp >> 2;

    wmma::fragment<wmma::accumulator, 16, 16, 16, float> c[2][4];
#pragma unroll
    for (int mi = 0; mi < 2; mi++)
#pragma unroll
        for (int ni = 0; ni < 4; ni++) wmma::fill_fragment(c[mi][ni], 0.0f);

    for (int k0 = 0; k0 < DINE; k0 += 64) {
        // A: 128x64 fp32 -> split -> bf16 hi/lo smem. 2048 float4 total.
#pragma unroll
        for (int it = 0; it < 8; it++) {
            int idx = tid + 256 * it;
            int r = idx >> 4, c4 = (idx & 15) * 4;
            float4 v = *(const float4*)&x[(size_t)(row0 + r) * DINE + k0 + c4];
            __nv_bfloat162 hh[2], ll[2];
            split4(v, hh, ll);
            *(__nv_bfloat162*)&sAh[r*ASTR + c4]     = hh[0];
            *(__nv_bfloat162*)&sAh[r*ASTR + c4 + 2] = hh[1];
            *(__nv_bfloat162*)&sAl[r*ASTR + c4]     = ll[0];
            *(__nv_bfloat162*)&sAl[r*ASTR + c4 + 2] = ll[1];
        }
        // B: 64k x 128cols (2 heads) hi+lo (pre-split)
#pragma unroll
        for (int it = 0; it < 4; it++) {
            int idx = tid + 256 * it;
            int r = idx >> 4, c8 = (idx & 15) * 8;
            int mh = mat * HN + h0 + (c8 >> 6);
            int d0 = c8 & 63;
            size_t src = ((size_t)mh * DINE + (k0 + r)) * DD + d0;
            *(uint4*)&sBh[r*BSTR2 + c8] = *(const uint4*)&g_w_hi[src];
            *(uint4*)&sBl[r*BSTR2 + c8] = *(const uint4*)&g_w_lo[src];
        }
        __syncthreads();

#pragma unroll
        for (int ks = 0; ks < 64; ks += 16) {
            wmma::fragment<wmma::matrix_a, 16, 16, 16, __nv_bfloat16, wmma::row_major> ah[2], al[2];
#pragma unroll
            for (int mi = 0; mi < 2; mi++) {
                wmma::load_matrix_sync(ah[mi], &sAh[(wm*32 + mi*16)*ASTR + ks], ASTR);
                wmma::load_matrix_sync(al[mi], &sAl[(wm*32 + mi*16)*ASTR + ks], ASTR);
            }
#pragma unroll
            for (int ni = 0; ni < 4; ni++) {
                wmma::fragment<wmma::matrix_b, 16, 16, 16, __nv_bfloat16, wmma::row_major> bh, bl;
                wmma::load_matrix_sync(bh, &sBh[ks*BSTR2 + wn*64 + ni*16], BSTR2);
                wmma::load_matrix_sync(bl, &sBl[ks*BSTR2 + wn*64 + ni*16], BSTR2);
#pragma unroll
                for (int mi = 0; mi < 2; mi++) {
                    wmma::mma_sync(c[mi][ni], ah[mi], bh, c[mi][ni]);
                    wmma::mma_sync(c[mi][ni], ah[mi], bl, c[mi][ni]);
                    wmma::mma_sync(c[mi][ni], al[mi], bh, c[mi][ni]);
                }
            }
        }
        __syncthreads();
    }

#pragma unroll
    for (int mi = 0; mi < 2; mi++)
#pragma unroll
        for (int ni = 0; ni < 4; ni++)
            wmma::store_matrix_sync(&sC[(wm*32 + mi*16)*132 + wn*64 + ni*16],
                                    c[mi][ni], 132, wmma::mem_row_major);
    __syncthreads();

    __nv_bfloat16* dh = (mat == 0 ? g_qh : mat == 1 ? g_kh : g_vh);
    __nv_bfloat16* dl = (mat == 0 ? g_ql : mat == 1 ? g_kl : g_vl);
    int n = row0 >> 10, t0 = row0 & (TT - 1);
#pragma unroll
    for (int it = 0; it < 8; it++) {
        int idx = tid + 256 * it;
        int r = idx >> 4, c8 = (idx & 15) * 8;
        int h = h0 + (c8 >> 6), d0 = c8 & 63;
        size_t base = ((size_t)(n*HN + h)*TT + t0 + r) * DD + d0;
        const float* src = &sC[r*132 + c8];
        __nv_bfloat162 hh[4], ll[4];
#pragma unroll
        for (int q = 0; q < 2; q++) {
            float4 v = *(const float4*)&src[4*q];
            split4(v, &hh[2*q], &ll[2*q]);
        }
        *(uint4*)&dh[base] = *(uint4*)hh;
        *(uint4*)&dl[base] = *(uint4*)ll;
    }
}

// ---------------------------------------------------------------------------
// S = Q @ K^T via WMMA bf16 split, per (bh, lower-tri 128x128 block).
// ---------------------------------------------------------------------------
#define QS 72
__global__ __launch_bounds__(256, 2) void sgemm_tc_kernel(float* __restrict__ attn)
{
    extern __shared__ __nv_bfloat16 smb[];
    __nv_bfloat16* sQh = smb;
    __nv_bfloat16* sQl = smb + 128*QS;
    __nv_bfloat16* sKh = smb + 2*128*QS;
    __nv_bfloat16* sKl = smb + 3*128*QS;

    int idx = blockIdx.x, rb = 0;
    while (idx > rb) { idx -= rb + 1; rb++; }
    int cb = idx;
    int bh = blockIdx.y;

    const __nv_bfloat16* qh = g_qh + ((size_t)bh * TT + rb*128) * DD;
    const __nv_bfloat16* ql = g_ql + ((size_t)bh * TT + rb*128) * DD;
    const __nv_bfloat16* kh = g_kh + ((size_t)bh * TT + cb*128) * DD;
    const __nv_bfloat16* kl = g_kl + ((size_t)bh * TT + cb*128) * DD;

    int tid = threadIdx.x, warp = tid >> 5;
    int wm = warp & 3, wn = warp >> 2;

#pragma unroll
    for (int it = 0; it < 4; it++) {
        int v = tid + 256 * it;
        int r = v >> 3, cc = (v & 7) * 8;
        *(uint4*)&sQh[r*QS + cc] = *(const uint4*)&qh[(size_t)r*DD + cc];
        *(uint4*)&sQl[r*QS + cc] = *(const uint4*)&ql[(size_t)r*DD + cc];
        *(uint4*)&sKh[r*QS + cc] = *(const uint4*)&kh[(size_t)r*DD + cc];
        *(uint4*)&sKl[r*QS + cc] = *(const uint4*)&kl[(size_t)r*DD + cc];
    }
    __syncthreads();

    wmma::fragment<wmma::accumulator, 16, 16, 16, float> c[2][4];
#pragma unroll
    for (int mi = 0; mi < 2; mi++)
#pragma unroll
        for (int ni = 0; ni < 4; ni++) wmma::fill_fragment(c[mi][ni], 0.0f);

#pragma unroll
    for (int k0 = 0; k0 < 64; k0 += 16) {
        wmma::fragment<wmma::matrix_a, 16, 16, 16, __nv_bfloat16, wmma::row_major> ah[2], al[2];
#pragma unroll
        for (int mi = 0; mi < 2; mi++) {
            wmma::load_matrix_sync(ah[mi], &sQh[(wm*32 + mi*16)*QS + k0], QS);
            wmma::load_matrix_sync(al[mi], &sQl[(wm*32 + mi*16)*QS + k0], QS);
        }
#pragma unroll
        for (int ni = 0; ni < 4; ni++) {
            wmma::fragment<wmma::matrix_b, 16, 16, 16, __nv_bfloat16, wmma::col_major> bh, bl;
            wmma::load_matrix_sync(bh, &sKh[(wn*64 + ni*16)*QS + k0], QS);
            wmma::load_matrix_sync(bl, &sKl[(wn*64 + ni*16)*QS + k0], QS);
#pragma unroll
            for (int mi = 0; mi < 2; mi++) {
                wmma::mma_sync(c[mi][ni], ah[mi], bh, c[mi][ni]);
                wmma::mma_sync(c[mi][ni], ah[mi], bl, c[mi][ni]);
                wmma::mma_sync(c[mi][ni], al[mi], bh, c[mi][ni]);
            }
        }
    }

#pragma unroll
    for (int mi = 0; mi < 2; mi++)
#pragma unroll
        for (int ni = 0; ni < 4; ni++) {
            int row = rb*128 + wm*32 + mi*16;
            int col = cb*128 + wn*64 + ni*16;
            wmma::store_matrix_sync(&attn[((size_t)bh*TT + row)*TT + col],
                                    c[mi][ni], TT, wmma::mem_row_major);
        }
}

// ---------------------------------------------------------------------------
// Softmax (causal + "==0 -> -inf"), one warp/row, float4, dead-block skip.
// ---------------------------------------------------------------------------
__global__ __launch_bounds__(256) void softmax_kernel(float* __restrict__ attn)
{
    int tid = threadIdx.x, lane = tid & 31, warp = tid >> 5;
    int tq = blockIdx.x * 8 + warp;
    int bh = blockIdx.y;
    float* row = attn + ((size_t)bh * TT + tq) * TT;
    int len = tq + 1;
    int jlim = (len + 127) >> 7;

    float4 pv4[8];
    float mx = -INFINITY;
#pragma unroll
    for (int j = 0; j < 8; j++) {
        if (j < jlim) {
            int base = j*128 + lane*4;
            float4 v = *(const float4*)&row[base];
            float* e = &v.x;
#pragma unroll
            for (int cq = 0; cq < 4; cq++) {
                float val = (base + cq < len) ? (e[cq] == 0.0f ? -INFINITY : e[cq])
                                              : -INFINITY;
                e[cq] = val;
                mx = fmaxf(mx, val);
            }
            pv4[j] = v;
        } else {
            pv4[j] = make_float4(0.f, 0.f, 0.f, 0.f);
        }
    }
#pragma unroll
    for (int o = 16; o > 0; o >>= 1) mx = fmaxf(mx, __shfl_xor_sync(0xffffffffu, mx, o));

    float sum = 0.f;
#pragma unroll
    for (int j = 0; j < 8; j++) {
        if (j < jlim) {
            int base = j*128 + lane*4;
            float* e = &pv4[j].x;
#pragma unroll
            for (int cq = 0; cq < 4; cq++) {
                float p = (base + cq < len) ? fexp(e[cq] - mx) : 0.0f;
                e[cq] = p;
                sum += p;
            }
        }
    }
#pragma unroll
    for (int o = 16; o > 0; o >>= 1) sum += __shfl_xor_sync(0xffffffffu, sum, o);
    float inv = 1.f / sum;

#pragma unroll
    for (int j = 0; j < 8; j++) {
        float4 v = pv4[j];
        v.x *= inv; v.y *= inv; v.z *= inv; v.w *= inv;
        *(float4*)&row[j*128 + lane*4] = v;
    }
}

// ---------------------------------------------------------------------------
// O = P @ V via WMMA, key-chunk 64. Epilogue writes bf16 hi/lo O.
// ---------------------------------------------------------------------------
#define PVS 72
#define PV_SMEM 55296   // P 2*128*72*2 + V 2*64*72*2; epi 128*68*4=34816 fits

__global__ __launch_bounds__(256) void pv_tc_kernel(const float* __restrict__ attn)
{
    extern __shared__ __align__(16) char dynp[];
    __nv_bfloat16* sPh = (__nv_bfloat16*)dynp;           // 128*PVS
    __nv_bfloat16* sPl = sPh + 128*PVS;
    __nv_bfloat16* sVh = sPl + 128*PVS;                  // 64*PVS
    __nv_bfloat16* sVl = sVh + 64*PVS;
    float* sC = (float*)dynp;                            // epi: 128 x 68

    int rb = 7 - blockIdx.x;
    int bh = blockIdx.y;
    int row0 = rb * 128;
    int kmax = (rb + 1) * 128;
    const float* pp = attn + ((size_t)bh * TT + row0) * TT;
    const __nv_bfloat16* vh = g_vh + (size_t)bh * TT * DD;
    const __nv_bfloat16* vl = g_vl + (size_t)bh * TT * DD;

    int tid = threadIdx.x, warp = tid >> 5;
    int wm = warp & 3, wn = warp >> 2;

    wmma::fragment<wmma::accumulator, 16, 16, 16, float> c[2][2];
#pragma unroll
    for (int mi = 0; mi < 2; mi++)
#pragma unroll
        for (int ni = 0; ni < 2; ni++) wmma::fill_fragment(c[mi][ni], 0.0f);

    for (int sb = 0; sb < kmax; sb += 64) {
#pragma unroll
        for (int it = 0; it < 8; it++) {
            int v = tid + 256 * it;
            int r = v >> 4, c4 = (v & 15) * 4;
            float4 p = *(const float4*)&pp[(size_t)r * TT + sb + c4];
            __nv_bfloat162 hh[2], ll[2];
            split4(p, hh, ll);
            *(__nv_bfloat162*)&sPh[r*PVS + c4]     = hh[0];
            *(__nv_bfloat162*)&sPh[r*PVS + c4 + 2] = hh[1];
            *(__nv_bfloat162*)&sPl[r*PVS + c4]     = ll[0];
            *(__nv_bfloat162*)&sPl[r*PVS + c4 + 2] = ll[1];
        }
#pragma unroll
        for (int it = 0; it < 2; it++) {
            int v = tid + 256 * it;
            int r = v >> 3, cc = (v & 7) * 8;
            *(uint4*)&sVh[r*PVS + cc] = *(const uint4*)&vh[(size_t)(sb + r)*DD + cc];
            *(uint4*)&sVl[r*PVS + cc] = *(const uint4*)&vl[(size_t)(sb + r)*DD + cc];
        }
        __syncthreads();

#pragma unroll
        for (int k0 = 0; k0 < 64; k0 += 16) {
            wmma::fragment<wmma::matrix_a, 16, 16, 16, __nv_bfloat16, wmma::row_major> ah[2], al[2];
#pragma unroll
            for (int mi = 0; mi < 2; mi++) {
                wmma::load_matrix_sync(ah[mi], &sPh[(wm*32 + mi*16)*PVS + k0], PVS);
                wmma::load_matrix_sync(al[mi], &sPl[(wm*32 + mi*16)*PVS + k0], PVS);
            }
#pragma unroll
            for (int ni = 0; ni < 2; ni++) {
                wmma::fragment<wmma::matrix_b, 16, 16, 16, __nv_bfloat16, wmma::row_major> bh, bl;
                wmma::load_matrix_sync(bh, &sVh[k0*PVS + wn*32 + ni*16], PVS);
                wmma::load_matrix_sync(bl, &sVl[k0*PVS + wn*32 + ni*16], PVS);
#pragma unroll
                for (int mi = 0; mi < 2; mi++) {
                    wmma::mma_sync(c[mi][ni], ah[mi], bh, c[mi][ni]);
                    wmma::mma_sync(c[mi][ni], ah[mi], bl, c[mi][ni]);
                    wmma::mma_sync(c[mi][ni], al[mi], bh, c[mi][ni]);
                }
            }
        }
        __syncthreads();
    }

    // Epilogue: frags -> smem fp32 -> bf16 hi/lo O
#pragma unroll
    for (int mi = 0; mi < 2; mi++)
#pragma unroll
        for (int ni = 0; ni < 2; ni++)
            wmma::store_matrix_sync(&sC[(wm*32 + mi*16)*68 + wn*32 + ni*16],
                                    c[mi][ni], 68, wmma::mem_row_major);
    __syncthreads();

    int n = bh / HN, h = bh % HN;
#pragma unroll
    for (int it = 0; it < 4; it++) {
        int idx = tid + 256 * it;
        int r = idx >> 3, d0 = (idx & 7) * 8;
        size_t base = ((size_t)(n*TT + row0 + r))*DINE + h*DD + d0;
        const float* src = &sC[r*68 + d0];
        __nv_bfloat162 hh[4], ll[4];
#pragma unroll
        for (int q = 0; q < 2; q++) {
            float4 v = *(const float4*)&src[4*q];
            split4(v, &hh[2*q], &ll[2*q]);
        }
        *(uint4*)&g_oh[base] = *(uint4*)hh;
        *(uint4*)&g_ol[base] = *(uint4*)ll;
    }
}

// ---------------------------------------------------------------------------
// Output projection via WMMA: out = O @ Wo + bo. grid 128 x 32 rows.
// ---------------------------------------------------------------------------
#define OP_SMEM 27648

__global__ __launch_bounds__(256) void oproj_tc_kernel(
    const float* __restrict__ bo, float* __restrict__ out)
{
    extern __shared__ __align__(16) char dyno[];
    __nv_bfloat16* sAh = (__nv_bfloat16*)dyno;           // 32*PVS
    __nv_bfloat16* sAl = sAh + 32*PVS;
    __nv_bfloat16* sBh = sAl + 32*PVS;                   // 64*PVS
    __nv_bfloat16* sBl = sBh + 64*PVS;
    float* sC = (float*)dyno;                            // epi: 32 x 68

    int row0 = blockIdx.x * 32;
    int tid = threadIdx.x, warp = tid >> 5;
    int wm = warp & 1, wn = warp >> 1;   // warp tile 16x16

    wmma::fragment<wmma::accumulator, 16, 16, 16, float> c;
    wmma::fill_fragment(c, 0.0f);

    for (int k0 = 0; k0 < DINE; k0 += 64) {
        {
            int r = tid >> 3, cc = (tid & 7) * 8;
            size_t src = (size_t)(row0 + r) * DINE + k0 + cc;
            *(uint4*)&sAh[r*PVS + cc] = *(const uint4*)&g_oh[src];
            *(uint4*)&sAl[r*PVS + cc] = *(const uint4*)&g_ol[src];
        }
#pragma unroll
        for (int it = 0; it < 2; it++) {
            int idx = tid + 256 * it;
            int r = idx >> 3, cc = (idx & 7) * 8;
            size_t src = (size_t)(k0 + r) * DD + cc;
            *(uint4*)&sBh[r*PVS + cc] = *(const uint4*)&g_wo_h[src];
            *(uint4*)&sBl[r*PVS + cc] = *(const uint4*)&g_wo_l[src];
        }
        __syncthreads();

#pragma unroll
        for (int ks = 0; ks < 64; ks += 16) {
            wmma::fragment<wmma::matrix_a, 16, 16, 16, __nv_bfloat16, wmma::row_major> ah, al;
            wmma::fragment<wmma::matrix_b, 16, 16, 16, __nv_bfloat16, wmma::row_major> bh, bl;
            wmma::load_matrix_sync(ah, &sAh[(wm*16)*PVS + ks], PVS);
            wmma::load_matrix_sync(al, &sAl[(wm*16)*PVS + ks], PVS);
            wmma::load_matrix_sync(bh, &sBh[ks*PVS + wn*16], PVS);
            wmma::load_matrix_sync(bl, &sBl[ks*PVS + wn*16], PVS);
            wmma::mma_sync(c, ah, bh, c);
            wmma::mma_sync(c, ah, bl, c);
            wmma::mma_sync(c, al, bh, c);
        }
        __syncthreads();
    }

    wmma::store_matrix_sync(&sC[(wm*16)*68 + wn*16], c, 68, wmma::mem_row_major);
    __syncthreads();

#pragma unroll
    for (int it = 0; it < 2; it++) {
        int idx = tid + 256 * it;
        int r = idx >> 4, c4 = (idx & 15) * 4;
        float4 b = *(const float4*)&bo[c4];
        const float* src = &sC[r*68 + c4];
        float4 v = make_float4(src[0]+b.x, src[1]+b.y, src[2]+b.z, src[3]+b.w);
        *(float4*)&out[(size_t)(row0 + r) * DD + c4] = v;
    }
}

// ---------------------------------------------------------------------------
extern "C" void kernel_launch(void* const* d_in, const int* in_sizes, int n_in,
                              void* d_out, int out_size)
{
    const float* x  = (const float*)d_in[0];
    const float* Wq = (const float*)d_in[1];
    const float* Wk = (const float*)d_in[2];
    const float* Wv = (const float*)d_in[3];
    const float* Wo = (const float*)d_in[4];
    const float* bo = (const float*)d_in[5];
    float* out = (float*)d_out;

    const long NTD = (long)NBB * TT * DD;
    float* attn = out + NTD;

    cudaFuncSetAttribute(qkv_tc_kernel, cudaFuncAttributeMaxDynamicSharedMemorySize, QKV_SMEM);
    int smem_s = 4 * 128 * QS * (int)sizeof(__nv_bfloat16);  // 73728
    cudaFuncSetAttribute(sgemm_tc_kernel, cudaFuncAttributeMaxDynamicSharedMemorySize, smem_s);
    cudaFuncSetAttribute(pv_tc_kernel, cudaFuncAttributeMaxDynamicSharedMemorySize, PV_SMEM);
    cudaFuncSetAttribute(oproj_tc_kernel, cudaFuncAttributeMaxDynamicSharedMemorySize, OP_SMEM);

    cvt_w_kernel<<<dim3(576, 3), 256>>>(Wq, Wk, Wv);
    cvt_wo_kernel<<<48, 256>>>(Wo);
    qkv_tc_kernel<<<dim3(32, 18), 256, QKV_SMEM>>>(x);
    sgemm_tc_kernel<<<dim3(36, NBH), 256, smem_s>>>(attn);
    softmax_kernel<<<dim3(128, NBH), 256>>>(attn);
    pv_tc_kernel<<<dim3(8, NBH), 256, PV_SMEM>>>(attn);
    oproj_tc_kernel<<<128, 256, OP_SMEM>>>(bo, out);
}